// round 12
// baseline (speedup 1.0000x reference)
#include <cuda_runtime.h>
#include <cuda_bf16.h>
#include <cstdint>
#include <math.h>

#define BB   2
#define SS   2048
#define DD   1024
#define HH   16
#define HDIM 64
#define MTOT (BB*SS)   // 4096

// ---------------- scratch (__device__ globals; device-side refs ONLY) ------
__device__ __align__(16) __nv_bfloat16 g_qhi[BB*HH*SS*HDIM];
__device__ __align__(16) __nv_bfloat16 g_khi[BB*HH*SS*HDIM];
__device__ __align__(16) __nv_bfloat16 g_vhi[BB*HH*SS*HDIM];
__device__ __align__(16) __nv_bfloat16 g_vlo[BB*HH*SS*HDIM];
__device__ __align__(16) __nv_bfloat16 g_xhi[MTOT*DD];
__device__ __align__(16) __nv_bfloat16 g_xlo[MTOT*DD];
__device__ __align__(16) __nv_bfloat16 g_whi[DD*DD];
__device__ __align__(16) __nv_bfloat16 g_wlo[DD*DD];

// ---------------- helpers ---------------------------------------------------
__device__ __forceinline__ void mma16816(float* c, const uint32_t* a, const uint32_t* b) {
    asm volatile(
        "mma.sync.aligned.m16n8k16.row.col.f32.bf16.bf16.f32 "
        "{%0,%1,%2,%3},{%4,%5,%6,%7},{%8,%9},{%0,%1,%2,%3};"
        : "+f"(c[0]), "+f"(c[1]), "+f"(c[2]), "+f"(c[3])
        : "r"(a[0]), "r"(a[1]), "r"(a[2]), "r"(a[3]), "r"(b[0]), "r"(b[1]));
}

__device__ __forceinline__ uint32_t pack_bf16x2(float lo, float hi) {
    uint32_t d;
    asm("cvt.rn.bf16x2.f32 %0, %1, %2;" : "=r"(d) : "f"(hi), "f"(lo));
    return d;
}
__device__ __forceinline__ void split_pair(float x, float y, uint32_t& ph, uint32_t& pl) {
    ph = pack_bf16x2(x, y);
    float tx = __uint_as_float(ph << 16);
    float ty = __uint_as_float(ph & 0xFFFF0000u);
    pl = pack_bf16x2(x - tx, y - ty);
}

// fast 2^f via FMA (no MUFU). f <= ~1, clamped at -80.
__device__ __forceinline__ float fast_exp2(float f) {
    f = fmaxf(f, -80.0f);
    float t2 = f + 12582912.0f;
    float r  = f - (t2 - 12582912.0f);
    float p  = 1.0f + r * (0.69314718f + r * (0.24022651f +
                   r * (0.05550411f + r * 0.00961813f)));
    uint32_t eb = (__float_as_uint(t2) << 23) - (0x4B400000u << 23);
    return __uint_as_float(__float_as_uint(p) + eb);
}

__device__ __forceinline__ uint32_t smem_u32(const void* p) {
    uint32_t a;
    asm("{ .reg .u64 t; cvta.to.shared.u64 t, %1; cvt.u32.u64 %0, t; }"
        : "=r"(a) : "l"(p));
    return a;
}
#define CP_ASYNC16(dst, src) \
    asm volatile("cp.async.cg.shared.global [%0], [%1], 16;" \
        :: "r"(dst), "l"(src) : "memory")
#define CP_COMMIT() asm volatile("cp.async.commit_group;" ::: "memory")
#define CP_WAIT0()  asm volatile("cp.async.wait_group 0;" ::: "memory")
#define CP_WAIT1()  asm volatile("cp.async.wait_group 1;" ::: "memory")

// ---------------- bf16 split conversion (inputs/weights) -------------------
__device__ __forceinline__ void split4(float4 v, uint2& hi, uint2& lo) {
    __nv_bfloat16 h0 = __float2bfloat16(v.x), h1 = __float2bfloat16(v.y);
    __nv_bfloat16 h2 = __float2bfloat16(v.z), h3 = __float2bfloat16(v.w);
    __nv_bfloat16 l0 = __float2bfloat16(v.x - __bfloat162float(h0));
    __nv_bfloat16 l1 = __float2bfloat16(v.y - __bfloat162float(h1));
    __nv_bfloat16 l2 = __float2bfloat16(v.z - __bfloat162float(h2));
    __nv_bfloat16 l3 = __float2bfloat16(v.w - __bfloat162float(h3));
    hi.x = ((uint32_t)__bfloat16_as_ushort(h1) << 16) | __bfloat16_as_ushort(h0);
    hi.y = ((uint32_t)__bfloat16_as_ushort(h3) << 16) | __bfloat16_as_ushort(h2);
    lo.x = ((uint32_t)__bfloat16_as_ushort(l1) << 16) | __bfloat16_as_ushort(l0);
    lo.y = ((uint32_t)__bfloat16_as_ushort(l3) << 16) | __bfloat16_as_ushort(l2);
}

__global__ __launch_bounds__(256) void convert_flat(
    const float* __restrict__ src, int which, int n4)
{
    int i = blockIdx.x * blockDim.x + threadIdx.x;
    if (i >= n4) return;
    __nv_bfloat16* __restrict__ hi = (which == 0) ? g_xhi : g_whi;
    __nv_bfloat16* __restrict__ lo = (which == 0) ? g_xlo : g_wlo;
    uint2 h, l;
    split4(((const float4*)src)[i], h, l);
    ((uint2*)hi)[i] = h;
    ((uint2*)lo)[i] = l;
}

// ---------------- HMMA GEMM: chunk-major 3-pass, double-buffered cp.async --
// K-chunk 64. Stage = {Ahi, Alo, Bhi, Blo}, each 128 rows x 64 bf16,
// row stride 144B (36 words == 4 mod 32 -> conflict-free fragment LDS).
#define GROWB 144
#define MAT_B (128*GROWB)        // 18432 per matrix
#define STG_B (4*MAT_B)          // 73728 per stage
#define SMEM_GEMM (2*STG_B)      // 147456

// fill one K-chunk (c in 0..15) into stage `buf`
__device__ __forceinline__ void g_fill(
    uint32_t sb, int buf, int c, int tid, int m0, int n0)
{
    const int kc = c * 64;
    const uint32_t st = sb + buf * STG_B;
    #pragma unroll
    for (int i = 0; i < 4; i++) {
        int t = tid + i * 256;
        int row = t >> 3, g = t & 7;
        uint32_t d = row * GROWB + g * 16;
        size_t ao = (size_t)(m0 + row) * DD + kc + g * 8;
        size_t bo = (size_t)(n0 + row) * DD + kc + g * 8;
        CP_ASYNC16(st +             d, (const void*)(g_xhi + ao));
        CP_ASYNC16(st + MAT_B     + d, (const void*)(g_xlo + ao));
        CP_ASYNC16(st + 2 * MAT_B + d, (const void*)(g_whi + bo));
        CP_ASYNC16(st + 3 * MAT_B + d, (const void*)(g_wlo + bo));
    }
}

template<int MODE>
__global__ __launch_bounds__(256) void gemm_tc(
    const float* __restrict__ bias, float* __restrict__ outp)
{
    extern __shared__ __align__(16) char sm[];
    const int tid = threadIdx.x, wid = tid >> 5, lid = tid & 31;
    const int n0 = blockIdx.x * 128, m0 = blockIdx.y * 128;
    const int wr = wid & 1;
    const int wc = wid >> 1;
    const uint32_t sb = smem_u32(sm);

    float acc[4][4][4] = {};

    g_fill(sb, 0, 0, tid, m0, n0);
    CP_COMMIT();

    for (int c = 0; c < 16; c++) {
        const int buf = c & 1;
        __syncthreads();   // compute(c-1) done reading buf^1 before refill
        if (c + 1 < 16) { g_fill(sb, buf ^ 1, c + 1, tid, m0, n0); CP_COMMIT(); }
        if (c + 1 < 16) CP_WAIT1(); else CP_WAIT0();
        __syncthreads();   // fill(c) visible

        const char* stg = sm + buf * STG_B;
        #pragma unroll
        for (int st = 0; st < 4; st++) {
            const int kbyte = st * 32 + (lid & 3) * 4;
            uint32_t ah[4][4], al[4][4], bh[4][2], bl[4][2];
            #pragma unroll
            for (int mt = 0; mt < 4; mt++) {
                const char* base = stg +
                    (wr * 64 + mt * 16 + (lid >> 2)) * GROWB + kbyte;
                ah[mt][0] = *(const uint32_t*)(base);
                ah[mt][1] = *(const uint32_t*)(base + 8 * GROWB);
                ah[mt][2] = *(const uint32_t*)(base + 16);
                ah[mt][3] = *(const uint32_t*)(base + 8 * GROWB + 16);
                al[mt][0] = *(const uint32_t*)(base + MAT_B);
                al[mt][1] = *(const uint32_t*)(base + MAT_B + 8 * GROWB);
                al[mt][2] = *(const uint32_t*)(base + MAT_B + 16);
                al[mt][3] = *(const uint32_t*)(base + MAT_B + 8 * GROWB + 16);
            }
            #pragma unroll
            for (int nt = 0; nt < 4; nt++) {
                const char* base = stg + 2 * MAT_B +
                    (wc * 32 + nt * 8 + (lid >> 2)) * GROWB + kbyte;
                bh[nt][0] = *(const uint32_t*)(base);
                bh[nt][1] = *(const uint32_t*)(base + 16);
                bl[nt][0] = *(const uint32_t*)(base + MAT_B);
                bl[nt][1] = *(const uint32_t*)(base + MAT_B + 16);
            }
            #pragma unroll
            for (int mt = 0; mt < 4; mt++)
                #pragma unroll
                for (int nt = 0; nt < 4; nt++) {
                    mma16816(acc[mt][nt], ah[mt], bh[nt]);
                    mma16816(acc[mt][nt], ah[mt], bl[nt]);
                    mma16816(acc[mt][nt], al[mt], bh[nt]);
                }
        }
    }

    // epilogue. MODE 0/1 (q,k): hi only. MODE 2 (v): hi+lo. MODE 3: fp32 out.
    #pragma unroll
    for (int mt = 0; mt < 4; mt++) {
        #pragma unroll
        for (int nt = 0; nt < 4; nt++) {
            int col = n0 + wc * 32 + nt * 8 + (lid & 3) * 2;
            float2 bv = *(const float2*)(bias + col);
            int r0 = m0 + wr * 64 + mt * 16 + (lid >> 2);
            #pragma unroll
            for (int half = 0; half < 2; half++) {
                int r = r0 + half * 8;
                float ox = acc[mt][nt][half * 2 + 0] + bv.x;
                float oy = acc[mt][nt][half * 2 + 1] + bv.y;
                if (MODE == 3) {
                    float2 o = {ox, oy};
                    *(float2*)(outp + (size_t)r * DD + col) = o;
                } else {
                    int b = r >> 11, s = r & (SS - 1);
                    int hh = col >> 6, hd = col & 63;
                    size_t off = (((size_t)(b * HH + hh)) * SS + s) * HDIM + hd;
                    uint32_t ph, pl;
                    split_pair(ox, oy, ph, pl);
                    if (MODE == 0) {
                        *(uint32_t*)(g_qhi + off) = ph;
                    } else if (MODE == 1) {
                        *(uint32_t*)(g_khi + off) = ph;
                    } else {
                        *(uint32_t*)(g_vhi + off) = ph;
                        *(uint32_t*)(g_vlo + off) = pl;
                    }
                }
            }
        }
    }
}

// ---------------- flash attention on mma.sync (proven R11 form) ------------
#define QROWB 144
#define VROWB 272
#define OFF_QHI 0
#define OFF_KHI 18432
#define OFF_VHI 36864
#define OFF_VLO 54272
#define SMEM_FLASH 71680

__device__ __forceinline__ void s_pass(
    float sf[16][4], const uint32_t a[4][4], const char* kb, int lid)
{
    #pragma unroll
    for (int nt = 0; nt < 16; nt++) {
        #pragma unroll
        for (int ks = 0; ks < 4; ks++) {
            const char* p = kb + (nt * 8 + (lid >> 2)) * QROWB + ks * 32 + (lid & 3) * 4;
            uint32_t bf[2] = { *(const uint32_t*)p, *(const uint32_t*)(p + 16) };
            mma16816(sf[nt], a[ks], bf);
        }
    }
}

__global__ __launch_bounds__(256, 1) void flash_mma()
{
    extern __shared__ __align__(16) char sm[];
    const int tid = threadIdx.x, wid = tid >> 5, lid = tid & 31;
    const int q0 = blockIdx.x * 128, h = blockIdx.y, b = blockIdx.z;
    const size_t base = ((size_t)(b * HH + h)) * SS * HDIM;
    const float cf = 0.18033688f;   // 0.125 * log2(e)

    #pragma unroll
    for (int i = 0; i < 4; i++) {
        int idx = tid + i * 256, row = idx >> 3, g = idx & 7;
        size_t src = base + (size_t)(q0 + row) * HDIM + g * 8;
        *(uint4*)(sm + OFF_QHI + row * QROWB + g * 16) = *(const uint4*)(g_qhi + src);
    }
    __syncthreads();

    uint32_t aQh[4][4];
    const int qrb = (wid * 16 + (lid >> 2)) * QROWB + (lid & 3) * 4;
    #pragma unroll
    for (int ks = 0; ks < 4; ks++) {
        const char* p = sm + OFF_QHI + qrb + ks * 32;
        aQh[ks][0] = *(const uint32_t*)(p);
        aQh[ks][1] = *(const uint32_t*)(p + 8 * QROWB);
        aQh[ks][2] = *(const uint32_t*)(p + 16);
        aQh[ks][3] = *(const uint32_t*)(p + 8 * QROWB + 16);
    }

    float acc[8][4] = {};
    float mrow[2] = {-1e30f, -1e30f}, lrow[2] = {0.f, 0.f};

    for (int kt0 = 0; kt0 < SS; kt0 += 128) {
        __syncthreads();

        #pragma unroll
        for (int i = 0; i < 4; i++) {
            int idx = tid + i * 256, row = idx >> 3, g = idx & 7;
            size_t src = base + (size_t)(kt0 + row) * HDIM + g * 8;
            *(uint4*)(sm + OFF_KHI + row * QROWB + g * 16) = *(const uint4*)(g_khi + src);
        }
        #pragma unroll
        for (int i = 0; i < 8; i++) {
            int idx = tid + i * 256, kt = idx >> 4, g = idx & 15;
            size_t src = base + (size_t)(kt0 + kt) * HDIM + g * 4;
            uint2 vh = *(const uint2*)(g_vhi + src);
            uint2 vl = *(const uint2*)(g_vlo + src);
            #pragma unroll
            for (int j = 0; j < 4; j++) {
                uint16_t hv = (j < 2) ? (uint16_t)(vh.x >> (j * 16))
                                      : (uint16_t)(vh.y >> ((j - 2) * 16));
                uint16_t lv = (j < 2) ? (uint16_t)(vl.x >> (j * 16))
                                      : (uint16_t)(vl.y >> ((j - 2) * 16));
                *(uint16_t*)(sm + OFF_VHI + (g * 4 + j) * VROWB + kt * 2) = hv;
                *(uint16_t*)(sm + OFF_VLO + (g * 4 + j) * VROWB + kt * 2) = lv;
            }
        }
        __syncthreads();

        float sf[16][4];
        #pragma unroll
        for (int nt = 0; nt < 16; nt++)
            sf[nt][0] = sf[nt][1] = sf[nt][2] = sf[nt][3] = 0.f;
        s_pass(sf, aQh, sm + OFF_KHI, lid);

        float corr[2];
        #pragma unroll
        for (int half = 0; half < 2; half++) {
            const int v0 = half * 2, v1 = half * 2 + 1;
            float tm = -1e30f;
            #pragma unroll
            for (int nt = 0; nt < 16; nt++)
                tm = fmaxf(tm, fmaxf(sf[nt][v0], sf[nt][v1]));
            tm = fmaxf(tm, __shfl_xor_sync(0xffffffffu, tm, 1));
            tm = fmaxf(tm, __shfl_xor_sync(0xffffffffu, tm, 2));
            float mn = fmaxf(mrow[half], tm * cf);
            corr[half] = fast_exp2(mrow[half] - mn);
            mrow[half] = mn;
            float sum = 0.f;
            #pragma unroll
            for (int nt = 0; nt < 16; nt++) {
                float p0 = fast_exp2(fmaf(sf[nt][v0], cf, -mn));
                float p1 = fast_exp2(fmaf(sf[nt][v1], cf, -mn));
                sf[nt][v0] = p0; sf[nt][v1] = p1;
                sum += p0 + p1;
            }
            sum += __shfl_xor_sync(0xffffffffu, sum, 1);
            sum += __shfl_xor_sync(0xffffffffu, sum, 2);
            lrow[half] = lrow[half] * corr[half] + sum;
        }
        #pragma unroll
        for (int nt = 0; nt < 8; nt++) {
            acc[nt][0] *= corr[0]; acc[nt][1] *= corr[0];
            acc[nt][2] *= corr[1]; acc[nt][3] *= corr[1];
        }

        uint32_t aPhi[8][4], aPlo[8][4];
        #pragma unroll
        for (int ks = 0; ks < 8; ks++) {
            split_pair(sf[2*ks  ][0], sf[2*ks  ][1], aPhi[ks][0], aPlo[ks][0]);
            split_pair(sf[2*ks  ][2], sf[2*ks  ][3], aPhi[ks][1], aPlo[ks][1]);
            split_pair(sf[2*ks+1][0], sf[2*ks+1][1], aPhi[ks][2], aPlo[ks][2]);
            split_pair(sf[2*ks+1][2], sf[2*ks+1][3], aPhi[ks][3], aPlo[ks][3]);
        }

        #pragma unroll
        for (int nt = 0; nt < 8; nt++) {
            #pragma unroll
            for (int ks = 0; ks < 8; ks++) {
                const char* ph = sm + OFF_VHI +
                    (nt * 8 + (lid >> 2)) * VROWB + ks * 32 + (lid & 3) * 4;
                uint32_t bh[2] = { *(const uint32_t*)ph, *(const uint32_t*)(ph + 16) };
                mma16816(acc[nt], aPhi[ks], bh);
                mma16816(acc[nt], aPlo[ks], bh);
                const char* pl = sm + OFF_VLO +
                    (nt * 8 + (lid >> 2)) * VROWB + ks * 32 + (lid & 3) * 4;
                uint32_t bl[2] = { *(const uint32_t*)pl, *(const uint32_t*)(pl + 16) };
                mma16816(acc[nt], aPhi[ks], bl);
            }
        }
    }

    float inv0 = 1.0f / lrow[0], inv1 = 1.0f / lrow[1];
    int r0 = q0 + wid * 16 + (lid >> 2);
    size_t m0 = (size_t)(b * SS + r0) * DD + h * HDIM;
    #pragma unroll
    for (int nt = 0; nt < 8; nt++) {
        int d = nt * 8 + 2 * (lid & 3);
        uint32_t ph, pl;
        split_pair(acc[nt][0] * inv0, acc[nt][1] * inv0, ph, pl);
        *(uint32_t*)(g_xhi + m0 + d) = ph;
        *(uint32_t*)(g_xlo + m0 + d) = pl;
        split_pair(acc[nt][2] * inv1, acc[nt][3] * inv1, ph, pl);
        *(uint32_t*)(g_xhi + m0 + 8 * DD + d) = ph;
        *(uint32_t*)(g_xlo + m0 + 8 * DD + d) = pl;
    }
}

// ---------------------------------------------------------------------------
extern "C" void kernel_launch(void* const* d_in, const int* in_sizes, int n_in,
                              void* d_out, int out_size)
{
    const float* Q  = (const float*)d_in[0];
    const float* K  = (const float*)d_in[1];
    const float* V  = (const float*)d_in[2];
    const float* Wq = (const float*)d_in[3];
    const float* bq = (const float*)d_in[4];
    const float* Wk = (const float*)d_in[5];
    const float* bk = (const float*)d_in[6];
    const float* Wv = (const float*)d_in[7];
    const float* bv = (const float*)d_in[8];
    const float* Wo = (const float*)d_in[9];
    const float* bo = (const float*)d_in[10];
    float* out = (float*)d_out;

    cudaFuncSetAttribute(gemm_tc<0>, cudaFuncAttributeMaxDynamicSharedMemorySize, SMEM_GEMM);
    cudaFuncSetAttribute(gemm_tc<1>, cudaFuncAttributeMaxDynamicSharedMemorySize, SMEM_GEMM);
    cudaFuncSetAttribute(gemm_tc<2>, cudaFuncAttributeMaxDynamicSharedMemorySize, SMEM_GEMM);
    cudaFuncSetAttribute(gemm_tc<3>, cudaFuncAttributeMaxDynamicSharedMemorySize, SMEM_GEMM);
    cudaFuncSetAttribute(flash_mma,  cudaFuncAttributeMaxDynamicSharedMemorySize, SMEM_FLASH);

    const int x4 = MTOT * DD / 4;
    const int w4 = DD * DD / 4;
    dim3 gg(DD / 128, MTOT / 128);  // (8, 32)

    convert_flat<<<x4 / 256, 256>>>(Q, 0, x4);
    convert_flat<<<w4 / 256, 256>>>(Wq, 1, w4);
    gemm_tc<0><<<gg, 256, SMEM_GEMM>>>(bq, nullptr);

    convert_flat<<<x4 / 256, 256>>>(K, 0, x4);
    convert_flat<<<w4 / 256, 256>>>(Wk, 1, w4);
    gemm_tc<1><<<gg, 256, SMEM_GEMM>>>(bk, nullptr);

    convert_flat<<<x4 / 256, 256>>>(V, 0, x4);
    convert_flat<<<w4 / 256, 256>>>(Wv, 1, w4);
    gemm_tc<2><<<gg, 256, SMEM_GEMM>>>(bv, nullptr);

    flash_mma<<<dim3(SS / 128, HH, BB), 256, SMEM_FLASH>>>();

    convert_flat<<<w4 / 256, 256>>>(Wo, 1, w4);
    gemm_tc<3><<<gg, 256, SMEM_GEMM>>>(bo, out);
}

// round 13
// speedup vs baseline: 1.6010x; 1.6010x over previous
#include <cuda_runtime.h>
#include <cuda_bf16.h>
#include <cstdint>
#include <math.h>

#define BB   2
#define SS   2048
#define DD   1024
#define HH   16
#define HDIM 64
#define MTOT (BB*SS)   // 4096

// ---------------- scratch (__device__ globals; device-side refs ONLY) ------
__device__ __align__(16) __nv_bfloat16 g_qhi[BB*HH*SS*HDIM];
__device__ __align__(16) __nv_bfloat16 g_khi[BB*HH*SS*HDIM];
__device__ __align__(16) __nv_bfloat16 g_vhi[BB*HH*SS*HDIM];
__device__ __align__(16) __nv_bfloat16 g_vlo[BB*HH*SS*HDIM];
__device__ __align__(16) __nv_bfloat16 g_xhi[MTOT*DD];
__device__ __align__(16) __nv_bfloat16 g_xlo[MTOT*DD];
__device__ __align__(16) __nv_bfloat16 g_whi[DD*DD];
__device__ __align__(16) __nv_bfloat16 g_wlo[DD*DD];

// ---------------- helpers ---------------------------------------------------
__device__ __forceinline__ void mma16816(float* c, const uint32_t* a, const uint32_t* b) {
    asm volatile(
        "mma.sync.aligned.m16n8k16.row.col.f32.bf16.bf16.f32 "
        "{%0,%1,%2,%3},{%4,%5,%6,%7},{%8,%9},{%0,%1,%2,%3};"
        : "+f"(c[0]), "+f"(c[1]), "+f"(c[2]), "+f"(c[3])
        : "r"(a[0]), "r"(a[1]), "r"(a[2]), "r"(a[3]), "r"(b[0]), "r"(b[1]));
}

__device__ __forceinline__ uint32_t pack_bf16x2(float lo, float hi) {
    uint32_t d;
    asm("cvt.rn.bf16x2.f32 %0, %1, %2;" : "=r"(d) : "f"(hi), "f"(lo));
    return d;
}
__device__ __forceinline__ void split_pair(float x, float y, uint32_t& ph, uint32_t& pl) {
    ph = pack_bf16x2(x, y);
    float tx = __uint_as_float(ph << 16);
    float ty = __uint_as_float(ph & 0xFFFF0000u);
    pl = pack_bf16x2(x - tx, y - ty);
}

// fast 2^f via FMA (no MUFU). f <= ~1, clamped at -80.
__device__ __forceinline__ float fast_exp2(float f) {
    f = fmaxf(f, -80.0f);
    float t2 = f + 12582912.0f;
    float r  = f - (t2 - 12582912.0f);
    float p  = 1.0f + r * (0.69314718f + r * (0.24022651f +
                   r * (0.05550411f + r * 0.00961813f)));
    uint32_t eb = (__float_as_uint(t2) << 23) - (0x4B400000u << 23);
    return __uint_as_float(__float_as_uint(p) + eb);
}

__device__ __forceinline__ uint32_t smem_u32(const void* p) {
    uint32_t a;
    asm("{ .reg .u64 t; cvta.to.shared.u64 t, %1; cvt.u32.u64 %0, t; }"
        : "=r"(a) : "l"(p));
    return a;
}
#define CP_ASYNC16(dst, src) \
    asm volatile("cp.async.cg.shared.global [%0], [%1], 16;" \
        :: "r"(dst), "l"(src) : "memory")
#define CP_COMMIT() asm volatile("cp.async.commit_group;" ::: "memory")
#define CP_WAIT0()  asm volatile("cp.async.wait_group 0;" ::: "memory")

// ---------------- bf16 split conversion (inputs/weights) -------------------
__device__ __forceinline__ void split4(float4 v, uint2& hi, uint2& lo) {
    __nv_bfloat16 h0 = __float2bfloat16(v.x), h1 = __float2bfloat16(v.y);
    __nv_bfloat16 h2 = __float2bfloat16(v.z), h3 = __float2bfloat16(v.w);
    __nv_bfloat16 l0 = __float2bfloat16(v.x - __bfloat162float(h0));
    __nv_bfloat16 l1 = __float2bfloat16(v.y - __bfloat162float(h1));
    __nv_bfloat16 l2 = __float2bfloat16(v.z - __bfloat162float(h2));
    __nv_bfloat16 l3 = __float2bfloat16(v.w - __bfloat162float(h3));
    hi.x = ((uint32_t)__bfloat16_as_ushort(h1) << 16) | __bfloat16_as_ushort(h0);
    hi.y = ((uint32_t)__bfloat16_as_ushort(h3) << 16) | __bfloat16_as_ushort(h2);
    lo.x = ((uint32_t)__bfloat16_as_ushort(l1) << 16) | __bfloat16_as_ushort(l0);
    lo.y = ((uint32_t)__bfloat16_as_ushort(l3) << 16) | __bfloat16_as_ushort(l2);
}

__global__ __launch_bounds__(256) void convert_flat(
    const float* __restrict__ src, int which, int n4)
{
    int i = blockIdx.x * blockDim.x + threadIdx.x;
    if (i >= n4) return;
    __nv_bfloat16* __restrict__ hi = (which == 0) ? g_xhi : g_whi;
    __nv_bfloat16* __restrict__ lo = (which == 0) ? g_xlo : g_wlo;
    uint2 h, l;
    split4(((const float4*)src)[i], h, l);
    ((uint2*)hi)[i] = h;
    ((uint2*)lo)[i] = l;
}

// ---------------- HMMA GEMM (reverted to proven R11 form) ------------------
// Pass-major 3-pass split, 128x128 tile, 69632 B smem -> 2 CTAs/SM.
#define ROWB 272
#define A_OFF 0
#define B_OFF (128*ROWB)
#define SMEM_GEMM (2*128*ROWB)   // 69632

template<int MODE>
__global__ __launch_bounds__(256) void gemm_tc(
    const float* __restrict__ bias, float* __restrict__ outp)
{
    extern __shared__ __align__(16) char sm[];
    const int tid = threadIdx.x, wid = tid >> 5, lid = tid & 31;
    const int n0 = blockIdx.x * 128, m0 = blockIdx.y * 128;
    const int wr = wid & 1;
    const int wc = wid >> 1;
    const uint32_t sb = smem_u32(sm);

    float acc[4][4][4] = {};

    const int cp_row = tid >> 4;
    const int cp_g   = tid & 15;

    for (int c = 0; c < 24; c++) {
        const int p  = c >> 3;
        const int kc = (c & 7) * 128;
        const __nv_bfloat16* __restrict__ As = (p < 2)  ? g_xhi : g_xlo;
        const __nv_bfloat16* __restrict__ Bs = (p == 1) ? g_wlo : g_whi;

        __syncthreads();
        #pragma unroll
        for (int i = 0; i < 8; i++) {
            int row = cp_row + i * 16;
            CP_ASYNC16(sb + A_OFF + row * ROWB + cp_g * 16,
                       (const void*)(As + (size_t)(m0 + row) * DD + kc + cp_g * 8));
            CP_ASYNC16(sb + B_OFF + row * ROWB + cp_g * 16,
                       (const void*)(Bs + (size_t)(n0 + row) * DD + kc + cp_g * 8));
        }
        CP_COMMIT();
        CP_WAIT0();
        __syncthreads();

        #pragma unroll
        for (int st = 0; st < 8; st++) {
            const int kbyte = st * 32 + (lid & 3) * 4;
            uint32_t af[4][4], bf[4][2];
            #pragma unroll
            for (int mt = 0; mt < 4; mt++) {
                const char* base = sm + A_OFF +
                    (wr * 64 + mt * 16 + (lid >> 2)) * ROWB + kbyte;
                af[mt][0] = *(const uint32_t*)(base);
                af[mt][1] = *(const uint32_t*)(base + 8 * ROWB);
                af[mt][2] = *(const uint32_t*)(base + 16);
                af[mt][3] = *(const uint32_t*)(base + 8 * ROWB + 16);
            }
            #pragma unroll
            for (int nt = 0; nt < 4; nt++) {
                const char* base = sm + B_OFF +
                    (wc * 32 + nt * 8 + (lid >> 2)) * ROWB + kbyte;
                bf[nt][0] = *(const uint32_t*)(base);
                bf[nt][1] = *(const uint32_t*)(base + 16);
            }
            #pragma unroll
            for (int mt = 0; mt < 4; mt++)
                #pragma unroll
                for (int nt = 0; nt < 4; nt++)
                    mma16816(acc[mt][nt], af[mt], bf[nt]);
        }
    }

    // epilogue. MODE 0/1 (q,k): hi only. MODE 2 (v): hi+lo. MODE 3: fp32 out.
    #pragma unroll
    for (int mt = 0; mt < 4; mt++) {
        #pragma unroll
        for (int nt = 0; nt < 4; nt++) {
            int col = n0 + wc * 32 + nt * 8 + (lid & 3) * 2;
            float2 bv = *(const float2*)(bias + col);
            int r0 = m0 + wr * 64 + mt * 16 + (lid >> 2);
            #pragma unroll
            for (int half = 0; half < 2; half++) {
                int r = r0 + half * 8;
                float ox = acc[mt][nt][half * 2 + 0] + bv.x;
                float oy = acc[mt][nt][half * 2 + 1] + bv.y;
                if (MODE == 3) {
                    float2 o = {ox, oy};
                    *(float2*)(outp + (size_t)r * DD + col) = o;
                } else {
                    int b = r >> 11, s = r & (SS - 1);
                    int hh = col >> 6, hd = col & 63;
                    size_t off = (((size_t)(b * HH + hh)) * SS + s) * HDIM + hd;
                    uint32_t ph, pl;
                    split_pair(ox, oy, ph, pl);
                    if (MODE == 0) {
                        *(uint32_t*)(g_qhi + off) = ph;
                    } else if (MODE == 1) {
                        *(uint32_t*)(g_khi + off) = ph;
                    } else {
                        *(uint32_t*)(g_vhi + off) = ph;
                        *(uint32_t*)(g_vlo + off) = pl;
                    }
                }
            }
        }
    }
}

// ---------------- flash attention on mma.sync ------------------------------
// R11 form + V-fill bank-conflict fix: warp spans 4 g x 8 kt instead of
// 16 g x 2 kt (old mapping hit 2 banks -> ~16-phase STS; new ~4-phase).
#define QROWB 144
#define VROWB 272
#define OFF_QHI 0
#define OFF_KHI 18432
#define OFF_VHI 36864
#define OFF_VLO 54272
#define SMEM_FLASH 71680

__device__ __forceinline__ void s_pass(
    float sf[16][4], const uint32_t a[4][4], const char* kb, int lid)
{
    #pragma unroll
    for (int nt = 0; nt < 16; nt++) {
        #pragma unroll
        for (int ks = 0; ks < 4; ks++) {
            const char* p = kb + (nt * 8 + (lid >> 2)) * QROWB + ks * 32 + (lid & 3) * 4;
            uint32_t bf[2] = { *(const uint32_t*)p, *(const uint32_t*)(p + 16) };
            mma16816(sf[nt], a[ks], bf);
        }
    }
}

__global__ __launch_bounds__(256, 1) void flash_mma()
{
    extern __shared__ __align__(16) char sm[];
    const int tid = threadIdx.x, wid = tid >> 5, lid = tid & 31;
    const int q0 = blockIdx.x * 128, h = blockIdx.y, b = blockIdx.z;
    const size_t base = ((size_t)(b * HH + h)) * SS * HDIM;
    const float cf = 0.18033688f;   // 0.125 * log2(e)

    #pragma unroll
    for (int i = 0; i < 4; i++) {
        int idx = tid + i * 256, row = idx >> 3, g = idx & 7;
        size_t src = base + (size_t)(q0 + row) * HDIM + g * 8;
        *(uint4*)(sm + OFF_QHI + row * QROWB + g * 16) = *(const uint4*)(g_qhi + src);
    }
    __syncthreads();

    uint32_t aQh[4][4];
    const int qrb = (wid * 16 + (lid >> 2)) * QROWB + (lid & 3) * 4;
    #pragma unroll
    for (int ks = 0; ks < 4; ks++) {
        const char* p = sm + OFF_QHI + qrb + ks * 32;
        aQh[ks][0] = *(const uint32_t*)(p);
        aQh[ks][1] = *(const uint32_t*)(p + 8 * QROWB);
        aQh[ks][2] = *(const uint32_t*)(p + 16);
        aQh[ks][3] = *(const uint32_t*)(p + 8 * QROWB + 16);
    }

    float acc[8][4] = {};
    float mrow[2] = {-1e30f, -1e30f}, lrow[2] = {0.f, 0.f};

    for (int kt0 = 0; kt0 < SS; kt0 += 128) {
        __syncthreads();

        // K chunk (hi only)
        #pragma unroll
        for (int i = 0; i < 4; i++) {
            int idx = tid + i * 256, row = idx >> 3, g = idx & 7;
            size_t src = base + (size_t)(kt0 + row) * HDIM + g * 8;
            *(uint4*)(sm + OFF_KHI + row * QROWB + g * 16) = *(const uint4*)(g_khi + src);
        }
        // V chunk transposed (hi/lo). New index split: idx bits
        // [1:0]|[8:7] -> g (0..15), [6:2]|[10:9] -> kt (0..127).
        // Warp = 4 g x 8 kt -> stores spread ~8 banks; loads stay 32B-chunked.
        #pragma unroll
        for (int i = 0; i < 8; i++) {
            int idx = tid + i * 256;
            int g  = (idx & 3) | (((idx >> 7) & 3) << 2);
            int kt = ((idx >> 2) & 31) | (((idx >> 9) & 3) << 5);
            size_t src = base + (size_t)(kt0 + kt) * HDIM + g * 4;
            uint2 vh = *(const uint2*)(g_vhi + src);
            uint2 vl = *(const uint2*)(g_vlo + src);
            #pragma unroll
            for (int j = 0; j < 4; j++) {
                uint16_t hv = (j < 2) ? (uint16_t)(vh.x >> (j * 16))
                                      : (uint16_t)(vh.y >> ((j - 2) * 16));
                uint16_t lv = (j < 2) ? (uint16_t)(vl.x >> (j * 16))
                                      : (uint16_t)(vl.y >> ((j - 2) * 16));
                *(uint16_t*)(sm + OFF_VHI + (g * 4 + j) * VROWB + kt * 2) = hv;
                *(uint16_t*)(sm + OFF_VLO + (g * 4 + j) * VROWB + kt * 2) = lv;
            }
        }
        __syncthreads();

        // S = Qhi Khi^T (single pass)
        float sf[16][4];
        #pragma unroll
        for (int nt = 0; nt < 16; nt++)
            sf[nt][0] = sf[nt][1] = sf[nt][2] = sf[nt][3] = 0.f;
        s_pass(sf, aQh, sm + OFF_KHI, lid);

        // online softmax
        float corr[2];
        #pragma unroll
        for (int half = 0; half < 2; half++) {
            const int v0 = half * 2, v1 = half * 2 + 1;
            float tm = -1e30f;
            #pragma unroll
            for (int nt = 0; nt < 16; nt++)
                tm = fmaxf(tm, fmaxf(sf[nt][v0], sf[nt][v1]));
            tm = fmaxf(tm, __shfl_xor_sync(0xffffffffu, tm, 1));
            tm = fmaxf(tm, __shfl_xor_sync(0xffffffffu, tm, 2));
            float mn = fmaxf(mrow[half], tm * cf);
            corr[half] = fast_exp2(mrow[half] - mn);
            mrow[half] = mn;
            float sum = 0.f;
            #pragma unroll
            for (int nt = 0; nt < 16; nt++) {
                float p0 = fast_exp2(fmaf(sf[nt][v0], cf, -mn));
                float p1 = fast_exp2(fmaf(sf[nt][v1], cf, -mn));
                sf[nt][v0] = p0; sf[nt][v1] = p1;
                sum += p0 + p1;
            }
            sum += __shfl_xor_sync(0xffffffffu, sum, 1);
            sum += __shfl_xor_sync(0xffffffffu, sum, 2);
            lrow[half] = lrow[half] * corr[half] + sum;
        }
        #pragma unroll
        for (int nt = 0; nt < 8; nt++) {
            acc[nt][0] *= corr[0]; acc[nt][1] *= corr[0];
            acc[nt][2] *= corr[1]; acc[nt][3] *= corr[1];
        }

        // pack P straight into A-fragments (register-resident, proven R11)
        uint32_t aPhi[8][4], aPlo[8][4];
        #pragma unroll
        for (int ks = 0; ks < 8; ks++) {
            split_pair(sf[2*ks  ][0], sf[2*ks  ][1], aPhi[ks][0], aPlo[ks][0]);
            split_pair(sf[2*ks  ][2], sf[2*ks  ][3], aPhi[ks][1], aPlo[ks][1]);
            split_pair(sf[2*ks+1][0], sf[2*ks+1][1], aPhi[ks][2], aPlo[ks][2]);
            split_pair(sf[2*ks+1][2], sf[2*ks+1][3], aPhi[ks][3], aPlo[ks][3]);
        }

        // acc += P @ V, 3 passes; Vhi fragments loaded once for both P passes
        #pragma unroll
        for (int nt = 0; nt < 8; nt++) {
            #pragma unroll
            for (int ks = 0; ks < 8; ks++) {
                const char* ph = sm + OFF_VHI +
                    (nt * 8 + (lid >> 2)) * VROWB + ks * 32 + (lid & 3) * 4;
                uint32_t bh[2] = { *(const uint32_t*)ph, *(const uint32_t*)(ph + 16) };
                mma16816(acc[nt], aPhi[ks], bh);
                mma16816(acc[nt], aPlo[ks], bh);
                const char* pl = sm + OFF_VLO +
                    (nt * 8 + (lid >> 2)) * VROWB + ks * 32 + (lid & 3) * 4;
                uint32_t bl[2] = { *(const uint32_t*)pl, *(const uint32_t*)(pl + 16) };
                mma16816(acc[nt], aPhi[ks], bl);
            }
        }
    }

    // epilogue: normalize, split, write ctx hi/lo row-major [M, D]
    float inv0 = 1.0f / lrow[0], inv1 = 1.0f / lrow[1];
    int r0 = q0 + wid * 16 + (lid >> 2);
    size_t m0 = (size_t)(b * SS + r0) * DD + h * HDIM;
    #pragma unroll
    for (int nt = 0; nt < 8; nt++) {
        int d = nt * 8 + 2 * (lid & 3);
        uint32_t ph, pl;
        split_pair(acc[nt][0] * inv0, acc[nt][1] * inv0, ph, pl);
        *(uint32_t*)(g_xhi + m0 + d) = ph;
        *(uint32_t*)(g_xlo + m0 + d) = pl;
        split_pair(acc[nt][2] * inv1, acc[nt][3] * inv1, ph, pl);
        *(uint32_t*)(g_xhi + m0 + 8 * DD + d) = ph;
        *(uint32_t*)(g_xlo + m0 + 8 * DD + d) = pl;
    }
}

// ---------------------------------------------------------------------------
extern "C" void kernel_launch(void* const* d_in, const int* in_sizes, int n_in,
                              void* d_out, int out_size)
{
    const float* Q  = (const float*)d_in[0];
    const float* K  = (const float*)d_in[1];
    const float* V  = (const float*)d_in[2];
    const float* Wq = (const float*)d_in[3];
    const float* bq = (const float*)d_in[4];
    const float* Wk = (const float*)d_in[5];
    const float* bk = (const float*)d_in[6];
    const float* Wv = (const float*)d_in[7];
    const float* bv = (const float*)d_in[8];
    const float* Wo = (const float*)d_in[9];
    const float* bo = (const float*)d_in[10];
    float* out = (float*)d_out;

    cudaFuncSetAttribute(gemm_tc<0>, cudaFuncAttributeMaxDynamicSharedMemorySize, SMEM_GEMM);
    cudaFuncSetAttribute(gemm_tc<1>, cudaFuncAttributeMaxDynamicSharedMemorySize, SMEM_GEMM);
    cudaFuncSetAttribute(gemm_tc<2>, cudaFuncAttributeMaxDynamicSharedMemorySize, SMEM_GEMM);
    cudaFuncSetAttribute(gemm_tc<3>, cudaFuncAttributeMaxDynamicSharedMemorySize, SMEM_GEMM);
    cudaFuncSetAttribute(flash_mma,  cudaFuncAttributeMaxDynamicSharedMemorySize, SMEM_FLASH);

    const int x4 = MTOT * DD / 4;
    const int w4 = DD * DD / 4;
    dim3 gg(DD / 128, MTOT / 128);  // (8, 32)

    convert_flat<<<x4 / 256, 256>>>(Q, 0, x4);
    convert_flat<<<w4 / 256, 256>>>(Wq, 1, w4);
    gemm_tc<0><<<gg, 256, SMEM_GEMM>>>(bq, nullptr);

    convert_flat<<<x4 / 256, 256>>>(K, 0, x4);
    convert_flat<<<w4 / 256, 256>>>(Wk, 1, w4);
    gemm_tc<1><<<gg, 256, SMEM_GEMM>>>(bk, nullptr);

    convert_flat<<<x4 / 256, 256>>>(V, 0, x4);
    convert_flat<<<w4 / 256, 256>>>(Wv, 1, w4);
    gemm_tc<2><<<gg, 256, SMEM_GEMM>>>(bv, nullptr);

    flash_mma<<<dim3(SS / 128, HH, BB), 256, SMEM_FLASH>>>();

    convert_flat<<<w4 / 256, 256>>>(Wo, 1, w4);
    gemm_tc<3><<<gg, 256, SMEM_GEMM>>>(bo, out);
}

// round 14
// speedup vs baseline: 1.6538x; 1.0330x over previous
#include <cuda_runtime.h>
#include <cuda_bf16.h>
#include <cstdint>
#include <math.h>

#define BB   2
#define SS   2048
#define DD   1024
#define HH   16
#define HDIM 64
#define MTOT (BB*SS)   // 4096
#define XSZ  (MTOT*DD) // 4M elems
#define WSZ  (DD*DD)   // 1M elems

// ---------------- scratch (__device__ globals; device-side refs ONLY) ------
__device__ __align__(16) __nv_bfloat16 g_axhi[3*XSZ];   // q,k,v input splits
__device__ __align__(16) __nv_bfloat16 g_axlo[3*XSZ];
__device__ __align__(16) __nv_bfloat16 g_w2hi[4*WSZ];   // wq,wk,wv,wo splits
__device__ __align__(16) __nv_bfloat16 g_w2lo[4*WSZ];
__device__ __align__(16) __nv_bfloat16 g_qhi[BB*HH*SS*HDIM];
__device__ __align__(16) __nv_bfloat16 g_khi[BB*HH*SS*HDIM];
__device__ __align__(16) __nv_bfloat16 g_vhi[BB*HH*SS*HDIM];
__device__ __align__(16) __nv_bfloat16 g_vlo[BB*HH*SS*HDIM];
__device__ __align__(16) __nv_bfloat16 g_xhi[XSZ];      // ctx from flash
__device__ __align__(16) __nv_bfloat16 g_xlo[XSZ];

// ---------------- helpers ---------------------------------------------------
__device__ __forceinline__ void mma16816(float* c, const uint32_t* a, const uint32_t* b) {
    asm volatile(
        "mma.sync.aligned.m16n8k16.row.col.f32.bf16.bf16.f32 "
        "{%0,%1,%2,%3},{%4,%5,%6,%7},{%8,%9},{%0,%1,%2,%3};"
        : "+f"(c[0]), "+f"(c[1]), "+f"(c[2]), "+f"(c[3])
        : "r"(a[0]), "r"(a[1]), "r"(a[2]), "r"(a[3]), "r"(b[0]), "r"(b[1]));
}

__device__ __forceinline__ uint32_t pack_bf16x2(float lo, float hi) {
    uint32_t d;
    asm("cvt.rn.bf16x2.f32 %0, %1, %2;" : "=r"(d) : "f"(hi), "f"(lo));
    return d;
}
__device__ __forceinline__ void split_pair(float x, float y, uint32_t& ph, uint32_t& pl) {
    ph = pack_bf16x2(x, y);
    float tx = __uint_as_float(ph << 16);
    float ty = __uint_as_float(ph & 0xFFFF0000u);
    pl = pack_bf16x2(x - tx, y - ty);
}

// fast 2^f via FMA (no MUFU). f <= ~1, clamped at -80.
__device__ __forceinline__ float fast_exp2(float f) {
    f = fmaxf(f, -80.0f);
    float t2 = f + 12582912.0f;
    float r  = f - (t2 - 12582912.0f);
    float p  = 1.0f + r * (0.69314718f + r * (0.24022651f +
                   r * (0.05550411f + r * 0.00961813f)));
    uint32_t eb = (__float_as_uint(t2) << 23) - (0x4B400000u << 23);
    return __uint_as_float(__float_as_uint(p) + eb);
}

__device__ __forceinline__ uint32_t smem_u32(const void* p) {
    uint32_t a;
    asm("{ .reg .u64 t; cvta.to.shared.u64 t, %1; cvt.u32.u64 %0, t; }"
        : "=r"(a) : "l"(p));
    return a;
}
#define CP_ASYNC16(dst, src) \
    asm volatile("cp.async.cg.shared.global [%0], [%1], 16;" \
        :: "r"(dst), "l"(src) : "memory")
#define CP_COMMIT() asm volatile("cp.async.commit_group;" ::: "memory")
#define CP_WAIT0()  asm volatile("cp.async.wait_group 0;" ::: "memory")
#define CP_WAIT1()  asm volatile("cp.async.wait_group 1;" ::: "memory")

// ---------------- bf16 split conversions ------------------------------------
__device__ __forceinline__ void split4(float4 v, uint2& hi, uint2& lo) {
    __nv_bfloat16 h0 = __float2bfloat16(v.x), h1 = __float2bfloat16(v.y);
    __nv_bfloat16 h2 = __float2bfloat16(v.z), h3 = __float2bfloat16(v.w);
    __nv_bfloat16 l0 = __float2bfloat16(v.x - __bfloat162float(h0));
    __nv_bfloat16 l1 = __float2bfloat16(v.y - __bfloat162float(h1));
    __nv_bfloat16 l2 = __float2bfloat16(v.z - __bfloat162float(h2));
    __nv_bfloat16 l3 = __float2bfloat16(v.w - __bfloat162float(h3));
    hi.x = ((uint32_t)__bfloat16_as_ushort(h1) << 16) | __bfloat16_as_ushort(h0);
    hi.y = ((uint32_t)__bfloat16_as_ushort(h3) << 16) | __bfloat16_as_ushort(h2);
    lo.x = ((uint32_t)__bfloat16_as_ushort(l1) << 16) | __bfloat16_as_ushort(l0);
    lo.y = ((uint32_t)__bfloat16_as_ushort(l3) << 16) | __bfloat16_as_ushort(l2);
}

// all three activations in one launch (z = blockIdx.y selects src + dst slab)
__global__ __launch_bounds__(256) void convert_act(
    const float* __restrict__ Q, const float* __restrict__ K,
    const float* __restrict__ V, int n4)
{
    int i = blockIdx.x * blockDim.x + threadIdx.x;
    if (i >= n4) return;
    int z = blockIdx.y;
    const float* src = (z == 0) ? Q : (z == 1) ? K : V;
    size_t off = (size_t)z * (XSZ / 4);
    uint2 h, l;
    split4(((const float4*)src)[i], h, l);
    ((uint2*)g_axhi)[off + i] = h;
    ((uint2*)g_axlo)[off + i] = l;
}

// all four weights in one launch
__global__ __launch_bounds__(256) void convert_w(
    const float* __restrict__ Wq, const float* __restrict__ Wk,
    const float* __restrict__ Wv, const float* __restrict__ Wo, int n4)
{
    int i = blockIdx.x * blockDim.x + threadIdx.x;
    if (i >= n4) return;
    int z = blockIdx.y;
    const float* src = (z == 0) ? Wq : (z == 1) ? Wk : (z == 2) ? Wv : Wo;
    size_t off = (size_t)z * (WSZ / 4);
    uint2 h, l;
    split4(((const float4*)src)[i], h, l);
    ((uint2*)g_w2hi)[off + i] = h;
    ((uint2*)g_w2lo)[off + i] = l;
}

// ---------------- GEMM core: pass-major 3-pass, K=64 double-buffered -------
// Stage = A(128x64) + B(128x64) bf16, row stride 144B (36 words == 4 mod 32
// -> conflict-free fragment LDS, same class as all proven layouts).
// 2 stages = 73728 B -> still 2 CTAs/SM (the R12 lesson).
#define GROWB 144
#define MATB  (128*GROWB)     // 18432
#define STG2  (2*MATB)        // 36864 per stage
#define SMEM_G2 (2*STG2)      // 73728

__device__ __forceinline__ void p_fill(
    uint32_t sb, int buf, int c, int tid, int m0, int n0,
    const __nv_bfloat16* __restrict__ Ahi, const __nv_bfloat16* __restrict__ Alo,
    const __nv_bfloat16* __restrict__ Bhi, const __nv_bfloat16* __restrict__ Blo)
{
    const int p  = c >> 4;          // pass 0: Ahi*Bhi, 1: Ahi*Blo, 2: Alo*Bhi
    const int kc = (c & 15) * 64;
    const __nv_bfloat16* A = (p < 2)  ? Ahi : Alo;
    const __nv_bfloat16* B = (p == 1) ? Blo : Bhi;
    const uint32_t st = sb + buf * STG2;
    #pragma unroll
    for (int i = 0; i < 4; i++) {
        int t = tid + i * 256;
        int row = t >> 3, g = t & 7;
        uint32_t d = row * GROWB + g * 16;
        CP_ASYNC16(st +        d, (const void*)(A + (size_t)(m0 + row) * DD + kc + g * 8));
        CP_ASYNC16(st + MATB + d, (const void*)(B + (size_t)(n0 + row) * DD + kc + g * 8));
    }
}

__device__ __forceinline__ void gemm_core(
    float acc[4][4][4], char* smp, uint32_t sb, int tid, int wr, int wc, int lid,
    int m0, int n0,
    const __nv_bfloat16* __restrict__ Ahi, const __nv_bfloat16* __restrict__ Alo,
    const __nv_bfloat16* __restrict__ Bhi, const __nv_bfloat16* __restrict__ Blo)
{
    p_fill(sb, 0, 0, tid, m0, n0, Ahi, Alo, Bhi, Blo);
    CP_COMMIT();

    for (int c = 0; c < 48; c++) {
        const int buf = c & 1;
        if (c + 1 < 48) {
            p_fill(sb, buf ^ 1, c + 1, tid, m0, n0, Ahi, Alo, Bhi, Blo);
            CP_COMMIT();
            CP_WAIT1();
        } else {
            CP_WAIT0();
        }
        __syncthreads();   // fill(c) visible; prev compute ended last iter

        const char* stg = smp + buf * STG2;
        #pragma unroll
        for (int st = 0; st < 4; st++) {
            const int kbyte = st * 32 + (lid & 3) * 4;
            uint32_t af[4][4], bf[4][2];
            #pragma unroll
            for (int mt = 0; mt < 4; mt++) {
                const char* base = stg +
                    (wr * 64 + mt * 16 + (lid >> 2)) * GROWB + kbyte;
                af[mt][0] = *(const uint32_t*)(base);
                af[mt][1] = *(const uint32_t*)(base + 8 * GROWB);
                af[mt][2] = *(const uint32_t*)(base + 16);
                af[mt][3] = *(const uint32_t*)(base + 8 * GROWB + 16);
            }
            #pragma unroll
            for (int nt = 0; nt < 4; nt++) {
                const char* base = stg + MATB +
                    (wc * 32 + nt * 8 + (lid >> 2)) * GROWB + kbyte;
                bf[nt][0] = *(const uint32_t*)(base);
                bf[nt][1] = *(const uint32_t*)(base + 16);
            }
            #pragma unroll
            for (int mt = 0; mt < 4; mt++)
                #pragma unroll
                for (int nt = 0; nt < 4; nt++)
                    mma16816(acc[mt][nt], af[mt], bf[nt]);
        }
        __syncthreads();   // all warps done with buf before it is refilled
    }
}

// z-batched Q/K/V projection: grid (8, 32, 3)
__global__ __launch_bounds__(256) void proj_tc(
    const float* __restrict__ bq, const float* __restrict__ bk,
    const float* __restrict__ bv)
{
    extern __shared__ __align__(16) char sm[];
    const int tid = threadIdx.x, wid = tid >> 5, lid = tid & 31;
    const int n0 = blockIdx.x * 128, m0 = blockIdx.y * 128;
    const int z  = blockIdx.z;
    const int wr = wid & 1, wc = wid >> 1;
    const uint32_t sb = smem_u32(sm);

    const __nv_bfloat16* Ahi = g_axhi + (size_t)z * XSZ;
    const __nv_bfloat16* Alo = g_axlo + (size_t)z * XSZ;
    const __nv_bfloat16* Bhi = g_w2hi + (size_t)z * WSZ;
    const __nv_bfloat16* Blo = g_w2lo + (size_t)z * WSZ;
    const float* bias = (z == 0) ? bq : (z == 1) ? bk : bv;

    float acc[4][4][4] = {};
    gemm_core(acc, sm, sb, tid, wr, wc, lid, m0, n0, Ahi, Alo, Bhi, Blo);

    #pragma unroll
    for (int mt = 0; mt < 4; mt++) {
        #pragma unroll
        for (int nt = 0; nt < 4; nt++) {
            int col = n0 + wc * 32 + nt * 8 + (lid & 3) * 2;
            float2 bvv = *(const float2*)(bias + col);
            int r0 = m0 + wr * 64 + mt * 16 + (lid >> 2);
            #pragma unroll
            for (int half = 0; half < 2; half++) {
                int r = r0 + half * 8;
                float ox = acc[mt][nt][half * 2 + 0] + bvv.x;
                float oy = acc[mt][nt][half * 2 + 1] + bvv.y;
                int b = r >> 11, s = r & (SS - 1);
                int hh = col >> 6, hd = col & 63;
                size_t off = (((size_t)(b * HH + hh)) * SS + s) * HDIM + hd;
                uint32_t ph, pl;
                split_pair(ox, oy, ph, pl);
                if (z == 0) {
                    *(uint32_t*)(g_qhi + off) = ph;
                } else if (z == 1) {
                    *(uint32_t*)(g_khi + off) = ph;
                } else {
                    *(uint32_t*)(g_vhi + off) = ph;
                    *(uint32_t*)(g_vlo + off) = pl;
                }
            }
        }
    }
}

// output projection: ctx (g_xhi/g_xlo) @ Wo^T + bo -> fp32 out
__global__ __launch_bounds__(256) void oproj_tc(
    const float* __restrict__ bias, float* __restrict__ outp)
{
    extern __shared__ __align__(16) char sm[];
    const int tid = threadIdx.x, wid = tid >> 5, lid = tid & 31;
    const int n0 = blockIdx.x * 128, m0 = blockIdx.y * 128;
    const int wr = wid & 1, wc = wid >> 1;
    const uint32_t sb = smem_u32(sm);

    float acc[4][4][4] = {};
    gemm_core(acc, sm, sb, tid, wr, wc, lid, m0, n0,
              g_xhi, g_xlo, g_w2hi + 3 * (size_t)WSZ, g_w2lo + 3 * (size_t)WSZ);

    #pragma unroll
    for (int mt = 0; mt < 4; mt++) {
        #pragma unroll
        for (int nt = 0; nt < 4; nt++) {
            int col = n0 + wc * 32 + nt * 8 + (lid & 3) * 2;
            float2 bvv = *(const float2*)(bias + col);
            int r0 = m0 + wr * 64 + mt * 16 + (lid >> 2);
            #pragma unroll
            for (int half = 0; half < 2; half++) {
                int r = r0 + half * 8;
                float2 o;
                o.x = acc[mt][nt][half * 2 + 0] + bvv.x;
                o.y = acc[mt][nt][half * 2 + 1] + bvv.y;
                *(float2*)(outp + (size_t)r * DD + col) = o;
            }
        }
    }
}

// ---------------- flash attention on mma.sync (proven R13 form) ------------
#define QROWB 144
#define VROWB 272
#define OFF_QHI 0
#define OFF_KHI 18432
#define OFF_VHI 36864
#define OFF_VLO 54272
#define SMEM_FLASH 71680

__device__ __forceinline__ void s_pass(
    float sf[16][4], const uint32_t a[4][4], const char* kb, int lid)
{
    #pragma unroll
    for (int nt = 0; nt < 16; nt++) {
        #pragma unroll
        for (int ks = 0; ks < 4; ks++) {
            const char* p = kb + (nt * 8 + (lid >> 2)) * QROWB + ks * 32 + (lid & 3) * 4;
            uint32_t bf[2] = { *(const uint32_t*)p, *(const uint32_t*)(p + 16) };
            mma16816(sf[nt], a[ks], bf);
        }
    }
}

__global__ __launch_bounds__(256, 1) void flash_mma()
{
    extern __shared__ __align__(16) char sm[];
    const int tid = threadIdx.x, wid = tid >> 5, lid = tid & 31;
    const int q0 = blockIdx.x * 128, h = blockIdx.y, b = blockIdx.z;
    const size_t base = ((size_t)(b * HH + h)) * SS * HDIM;
    const float cf = 0.18033688f;   // 0.125 * log2(e)

    #pragma unroll
    for (int i = 0; i < 4; i++) {
        int idx = tid + i * 256, row = idx >> 3, g = idx & 7;
        size_t src = base + (size_t)(q0 + row) * HDIM + g * 8;
        *(uint4*)(sm + OFF_QHI + row * QROWB + g * 16) = *(const uint4*)(g_qhi + src);
    }
    __syncthreads();

    uint32_t aQh[4][4];
    const int qrb = (wid * 16 + (lid >> 2)) * QROWB + (lid & 3) * 4;
    #pragma unroll
    for (int ks = 0; ks < 4; ks++) {
        const char* p = sm + OFF_QHI + qrb + ks * 32;
        aQh[ks][0] = *(const uint32_t*)(p);
        aQh[ks][1] = *(const uint32_t*)(p + 8 * QROWB);
        aQh[ks][2] = *(const uint32_t*)(p + 16);
        aQh[ks][3] = *(const uint32_t*)(p + 8 * QROWB + 16);
    }

    float acc[8][4] = {};
    float mrow[2] = {-1e30f, -1e30f}, lrow[2] = {0.f, 0.f};

    for (int kt0 = 0; kt0 < SS; kt0 += 128) {
        __syncthreads();

        #pragma unroll
        for (int i = 0; i < 4; i++) {
            int idx = tid + i * 256, row = idx >> 3, g = idx & 7;
            size_t src = base + (size_t)(kt0 + row) * HDIM + g * 8;
            *(uint4*)(sm + OFF_KHI + row * QROWB + g * 16) = *(const uint4*)(g_khi + src);
        }
        // V transpose fill, conflict-mitigated mapping (4 g x 8 kt per warp)
        #pragma unroll
        for (int i = 0; i < 8; i++) {
            int idx = tid + i * 256;
            int g  = (idx & 3) | (((idx >> 7) & 3) << 2);
            int kt = ((idx >> 2) & 31) | (((idx >> 9) & 3) << 5);
            size_t src = base + (size_t)(kt0 + kt) * HDIM + g * 4;
            uint2 vh = *(const uint2*)(g_vhi + src);
            uint2 vl = *(const uint2*)(g_vlo + src);
            #pragma unroll
            for (int j = 0; j < 4; j++) {
                uint16_t hv = (j < 2) ? (uint16_t)(vh.x >> (j * 16))
                                      : (uint16_t)(vh.y >> ((j - 2) * 16));
                uint16_t lv = (j < 2) ? (uint16_t)(vl.x >> (j * 16))
                                      : (uint16_t)(vl.y >> ((j - 2) * 16));
                *(uint16_t*)(sm + OFF_VHI + (g * 4 + j) * VROWB + kt * 2) = hv;
                *(uint16_t*)(sm + OFF_VLO + (g * 4 + j) * VROWB + kt * 2) = lv;
            }
        }
        __syncthreads();

        float sf[16][4];
        #pragma unroll
        for (int nt = 0; nt < 16; nt++)
            sf[nt][0] = sf[nt][1] = sf[nt][2] = sf[nt][3] = 0.f;
        s_pass(sf, aQh, sm + OFF_KHI, lid);

        float corr[2];
        #pragma unroll
        for (int half = 0; half < 2; half++) {
            const int v0 = half * 2, v1 = half * 2 + 1;
            float tm = -1e30f;
            #pragma unroll
            for (int nt = 0; nt < 16; nt++)
                tm = fmaxf(tm, fmaxf(sf[nt][v0], sf[nt][v1]));
            tm = fmaxf(tm, __shfl_xor_sync(0xffffffffu, tm, 1));
            tm = fmaxf(tm, __shfl_xor_sync(0xffffffffu, tm, 2));
            float mn = fmaxf(mrow[half], tm * cf);
            corr[half] = fast_exp2(mrow[half] - mn);
            mrow[half] = mn;
            float sum = 0.f;
            #pragma unroll
            for (int nt = 0; nt < 16; nt++) {
                float p0 = fast_exp2(fmaf(sf[nt][v0], cf, -mn));
                float p1 = fast_exp2(fmaf(sf[nt][v1], cf, -mn));
                sf[nt][v0] = p0; sf[nt][v1] = p1;
                sum += p0 + p1;
            }
            sum += __shfl_xor_sync(0xffffffffu, sum, 1);
            sum += __shfl_xor_sync(0xffffffffu, sum, 2);
            lrow[half] = lrow[half] * corr[half] + sum;
        }
        #pragma unroll
        for (int nt = 0; nt < 8; nt++) {
            acc[nt][0] *= corr[0]; acc[nt][1] *= corr[0];
            acc[nt][2] *= corr[1]; acc[nt][3] *= corr[1];
        }

        uint32_t aPhi[8][4], aPlo[8][4];
        #pragma unroll
        for (int ks = 0; ks < 8; ks++) {
            split_pair(sf[2*ks  ][0], sf[2*ks  ][1], aPhi[ks][0], aPlo[ks][0]);
            split_pair(sf[2*ks  ][2], sf[2*ks  ][3], aPhi[ks][1], aPlo[ks][1]);
            split_pair(sf[2*ks+1][0], sf[2*ks+1][1], aPhi[ks][2], aPlo[ks][2]);
            split_pair(sf[2*ks+1][2], sf[2*ks+1][3], aPhi[ks][3], aPlo[ks][3]);
        }

        #pragma unroll
        for (int nt = 0; nt < 8; nt++) {
            #pragma unroll
            for (int ks = 0; ks < 8; ks++) {
                const char* ph = sm + OFF_VHI +
                    (nt * 8 + (lid >> 2)) * VROWB + ks * 32 + (lid & 3) * 4;
                uint32_t bh[2] = { *(const uint32_t*)ph, *(const uint32_t*)(ph + 16) };
                mma16816(acc[nt], aPhi[ks], bh);
                mma16816(acc[nt], aPlo[ks], bh);
                const char* pl = sm + OFF_VLO +
                    (nt * 8 + (lid >> 2)) * VROWB + ks * 32 + (lid & 3) * 4;
                uint32_t bl[2] = { *(const uint32_t*)pl, *(const uint32_t*)(pl + 16) };
                mma16816(acc[nt], aPhi[ks], bl);
            }
        }
    }

    float inv0 = 1.0f / lrow[0], inv1 = 1.0f / lrow[1];
    int r0 = q0 + wid * 16 + (lid >> 2);
    size_t m0 = (size_t)(b * SS + r0) * DD + h * HDIM;
    #pragma unroll
    for (int nt = 0; nt < 8; nt++) {
        int d = nt * 8 + 2 * (lid & 3);
        uint32_t ph, pl;
        split_pair(acc[nt][0] * inv0, acc[nt][1] * inv0, ph, pl);
        *(uint32_t*)(g_xhi + m0 + d) = ph;
        *(uint32_t*)(g_xlo + m0 + d) = pl;
        split_pair(acc[nt][2] * inv1, acc[nt][3] * inv1, ph, pl);
        *(uint32_t*)(g_xhi + m0 + 8 * DD + d) = ph;
        *(uint32_t*)(g_xlo + m0 + 8 * DD + d) = pl;
    }
}

// ---------------------------------------------------------------------------
extern "C" void kernel_launch(void* const* d_in, const int* in_sizes, int n_in,
                              void* d_out, int out_size)
{
    const float* Q  = (const float*)d_in[0];
    const float* K  = (const float*)d_in[1];
    const float* V  = (const float*)d_in[2];
    const float* Wq = (const float*)d_in[3];
    const float* bq = (const float*)d_in[4];
    const float* Wk = (const float*)d_in[5];
    const float* bk = (const float*)d_in[6];
    const float* Wv = (const float*)d_in[7];
    const float* bv = (const float*)d_in[8];
    const float* Wo = (const float*)d_in[9];
    const float* bo = (const float*)d_in[10];
    float* out = (float*)d_out;

    cudaFuncSetAttribute(proj_tc,   cudaFuncAttributeMaxDynamicSharedMemorySize, SMEM_G2);
    cudaFuncSetAttribute(oproj_tc,  cudaFuncAttributeMaxDynamicSharedMemorySize, SMEM_G2);
    cudaFuncSetAttribute(flash_mma, cudaFuncAttributeMaxDynamicSharedMemorySize, SMEM_FLASH);

    const int x4 = XSZ / 4;   // 1048576
    const int w4 = WSZ / 4;   // 262144

    convert_act<<<dim3(x4 / 256, 3), 256>>>(Q, K, V, x4);
    convert_w<<<dim3(w4 / 256, 4), 256>>>(Wq, Wk, Wv, Wo, w4);

    proj_tc<<<dim3(DD / 128, MTOT / 128, 3), 256, SMEM_G2>>>(bq, bk, bv);

    flash_mma<<<dim3(SS / 128, HH, BB), 256, SMEM_FLASH>>>();

    oproj_tc<<<dim3(DD / 128, MTOT / 128), 256, SMEM_G2>>>(bo, out);
}

// round 16
// speedup vs baseline: 1.6838x; 1.0181x over previous
#include <cuda_runtime.h>
#include <cuda_bf16.h>
#include <cstdint>
#include <math.h>

#define BB   2
#define SS   2048
#define DD   1024
#define HH   16
#define HDIM 64
#define MTOT (BB*SS)   // 4096
#define XSZ  (MTOT*DD) // 4M elems
#define WSZ  (DD*DD)   // 1M elems

// ---------------- scratch (__device__ globals; device-side refs ONLY) ------
__device__ __align__(16) __nv_bfloat16 g_axhi[3*XSZ];   // q,k,v input splits
__device__ __align__(16) __nv_bfloat16 g_axlo[3*XSZ];
__device__ __align__(16) __nv_bfloat16 g_w2hi[4*WSZ];   // wq,wk,wv,wo splits
__device__ __align__(16) __nv_bfloat16 g_w2lo[4*WSZ];
__device__ __align__(16) __nv_bfloat16 g_qhi[BB*HH*SS*HDIM];
__device__ __align__(16) __nv_bfloat16 g_khi[BB*HH*SS*HDIM];
__device__ __align__(16) __nv_bfloat16 g_vhi[BB*HH*SS*HDIM];
__device__ __align__(16) __nv_bfloat16 g_vlo[BB*HH*SS*HDIM];
__device__ __align__(16) __nv_bfloat16 g_xhi[XSZ];      // ctx from flash
__device__ __align__(16) __nv_bfloat16 g_xlo[XSZ];

// ---------------- helpers ---------------------------------------------------
__device__ __forceinline__ void mma16816(float* c, const uint32_t* a, const uint32_t* b) {
    asm volatile(
        "mma.sync.aligned.m16n8k16.row.col.f32.bf16.bf16.f32 "
        "{%0,%1,%2,%3},{%4,%5,%6,%7},{%8,%9},{%0,%1,%2,%3};"
        : "+f"(c[0]), "+f"(c[1]), "+f"(c[2]), "+f"(c[3])
        : "r"(a[0]), "r"(a[1]), "r"(a[2]), "r"(a[3]), "r"(b[0]), "r"(b[1]));
}

__device__ __forceinline__ uint32_t pack_bf16x2(float lo, float hi) {
    uint32_t d;
    asm("cvt.rn.bf16x2.f32 %0, %1, %2;" : "=r"(d) : "f"(hi), "f"(lo));
    return d;
}
__device__ __forceinline__ void split_pair(float x, float y, uint32_t& ph, uint32_t& pl) {
    ph = pack_bf16x2(x, y);
    float tx = __uint_as_float(ph << 16);
    float ty = __uint_as_float(ph & 0xFFFF0000u);
    pl = pack_bf16x2(x - tx, y - ty);
}

// fast 2^f via FMA (no MUFU). f <= ~1, clamped at -80.
__device__ __forceinline__ float fast_exp2(float f) {
    f = fmaxf(f, -80.0f);
    float t2 = f + 12582912.0f;
    float r  = f - (t2 - 12582912.0f);
    float p  = 1.0f + r * (0.69314718f + r * (0.24022651f +
                   r * (0.05550411f + r * 0.00961813f)));
    uint32_t eb = (__float_as_uint(t2) << 23) - (0x4B400000u << 23);
    return __uint_as_float(__float_as_uint(p) + eb);
}

__device__ __forceinline__ uint32_t smem_u32(const void* p) {
    uint32_t a;
    asm("{ .reg .u64 t; cvta.to.shared.u64 t, %1; cvt.u32.u64 %0, t; }"
        : "=r"(a) : "l"(p));
    return a;
}
#define CP_ASYNC16(dst, src) \
    asm volatile("cp.async.cg.shared.global [%0], [%1], 16;" \
        :: "r"(dst), "l"(src) : "memory")
#define CP_COMMIT() asm volatile("cp.async.commit_group;" ::: "memory")
#define CP_WAIT0()  asm volatile("cp.async.wait_group 0;" ::: "memory")
#define CP_WAIT1()  asm volatile("cp.async.wait_group 1;" ::: "memory")

// ---------------- bf16 split conversions ------------------------------------
__device__ __forceinline__ void split4(float4 v, uint2& hi, uint2& lo) {
    __nv_bfloat16 h0 = __float2bfloat16(v.x), h1 = __float2bfloat16(v.y);
    __nv_bfloat16 h2 = __float2bfloat16(v.z), h3 = __float2bfloat16(v.w);
    __nv_bfloat16 l0 = __float2bfloat16(v.x - __bfloat162float(h0));
    __nv_bfloat16 l1 = __float2bfloat16(v.y - __bfloat162float(h1));
    __nv_bfloat16 l2 = __float2bfloat16(v.z - __bfloat162float(h2));
    __nv_bfloat16 l3 = __float2bfloat16(v.w - __bfloat162float(h3));
    hi.x = ((uint32_t)__bfloat16_as_ushort(h1) << 16) | __bfloat16_as_ushort(h0);
    hi.y = ((uint32_t)__bfloat16_as_ushort(h3) << 16) | __bfloat16_as_ushort(h2);
    lo.x = ((uint32_t)__bfloat16_as_ushort(l1) << 16) | __bfloat16_as_ushort(l0);
    lo.y = ((uint32_t)__bfloat16_as_ushort(l3) << 16) | __bfloat16_as_ushort(l2);
}

__global__ __launch_bounds__(256) void convert_act(
    const float* __restrict__ Q, const float* __restrict__ K,
    const float* __restrict__ V, int n4)
{
    int i = blockIdx.x * blockDim.x + threadIdx.x;
    if (i >= n4) return;
    int z = blockIdx.y;
    const float* src = (z == 0) ? Q : (z == 1) ? K : V;
    size_t off = (size_t)z * (XSZ / 4);
    uint2 h, l;
    split4(((const float4*)src)[i], h, l);
    ((uint2*)g_axhi)[off + i] = h;
    ((uint2*)g_axlo)[off + i] = l;
}

__global__ __launch_bounds__(256) void convert_w(
    const float* __restrict__ Wq, const float* __restrict__ Wk,
    const float* __restrict__ Wv, const float* __restrict__ Wo, int n4)
{
    int i = blockIdx.x * blockDim.x + threadIdx.x;
    if (i >= n4) return;
    int z = blockIdx.y;
    const float* src = (z == 0) ? Wq : (z == 1) ? Wk : (z == 2) ? Wv : Wo;
    size_t off = (size_t)z * (WSZ / 4);
    uint2 h, l;
    split4(((const float4*)src)[i], h, l);
    ((uint2*)g_w2hi)[off + i] = h;
    ((uint2*)g_w2lo)[off + i] = l;
}

// ---------------- GEMM core (proven R14): pass-major, K=64 double-buffer ---
#define GROWB 144
#define MATB  (128*GROWB)     // 18432
#define STG2  (2*MATB)        // 36864 per stage
#define SMEM_G2 (2*STG2)      // 73728

__device__ __forceinline__ void p_fill(
    uint32_t sb, int buf, int c, int tid, int m0, int n0,
    const __nv_bfloat16* __restrict__ Ahi, const __nv_bfloat16* __restrict__ Alo,
    const __nv_bfloat16* __restrict__ Bhi, const __nv_bfloat16* __restrict__ Blo)
{
    const int p  = c >> 4;
    const int kc = (c & 15) * 64;
    const __nv_bfloat16* A = (p < 2)  ? Ahi : Alo;
    const __nv_bfloat16* B = (p == 1) ? Blo : Bhi;
    const uint32_t st = sb + buf * STG2;
    #pragma unroll
    for (int i = 0; i < 4; i++) {
        int t = tid + i * 256;
        int row = t >> 3, g = t & 7;
        uint32_t d = row * GROWB + g * 16;
        CP_ASYNC16(st +        d, (const void*)(A + (size_t)(m0 + row) * DD + kc + g * 8));
        CP_ASYNC16(st + MATB + d, (const void*)(B + (size_t)(n0 + row) * DD + kc + g * 8));
    }
}

__device__ __forceinline__ void gemm_core(
    float acc[4][4][4], char* smp, uint32_t sb, int tid, int wr, int wc, int lid,
    int m0, int n0,
    const __nv_bfloat16* __restrict__ Ahi, const __nv_bfloat16* __restrict__ Alo,
    const __nv_bfloat16* __restrict__ Bhi, const __nv_bfloat16* __restrict__ Blo)
{
    p_fill(sb, 0, 0, tid, m0, n0, Ahi, Alo, Bhi, Blo);
    CP_COMMIT();

    for (int c = 0; c < 48; c++) {
        const int buf = c & 1;
        if (c + 1 < 48) {
            p_fill(sb, buf ^ 1, c + 1, tid, m0, n0, Ahi, Alo, Bhi, Blo);
            CP_COMMIT();
            CP_WAIT1();
        } else {
            CP_WAIT0();
        }
        __syncthreads();

        const char* stg = smp + buf * STG2;
        #pragma unroll
        for (int st = 0; st < 4; st++) {
            const int kbyte = st * 32 + (lid & 3) * 4;
            uint32_t af[4][4], bf[4][2];
            #pragma unroll
            for (int mt = 0; mt < 4; mt++) {
                const char* base = stg +
                    (wr * 64 + mt * 16 + (lid >> 2)) * GROWB + kbyte;
                af[mt][0] = *(const uint32_t*)(base);
                af[mt][1] = *(const uint32_t*)(base + 8 * GROWB);
                af[mt][2] = *(const uint32_t*)(base + 16);
                af[mt][3] = *(const uint32_t*)(base + 8 * GROWB + 16);
            }
            #pragma unroll
            for (int nt = 0; nt < 4; nt++) {
                const char* base = stg + MATB +
                    (wc * 32 + nt * 8 + (lid >> 2)) * GROWB + kbyte;
                bf[nt][0] = *(const uint32_t*)(base);
                bf[nt][1] = *(const uint32_t*)(base + 16);
            }
            #pragma unroll
            for (int mt = 0; mt < 4; mt++)
                #pragma unroll
                for (int nt = 0; nt < 4; nt++)
                    mma16816(acc[mt][nt], af[mt], bf[nt]);
        }
        __syncthreads();
    }
}

__global__ __launch_bounds__(256) void proj_tc(
    const float* __restrict__ bq, const float* __restrict__ bk,
    const float* __restrict__ bv)
{
    extern __shared__ __align__(16) char sm[];
    const int tid = threadIdx.x, wid = tid >> 5, lid = tid & 31;
    const int n0 = blockIdx.x * 128, m0 = blockIdx.y * 128;
    const int z  = blockIdx.z;
    const int wr = wid & 1, wc = wid >> 1;
    const uint32_t sb = smem_u32(sm);

    const __nv_bfloat16* Ahi = g_axhi + (size_t)z * XSZ;
    const __nv_bfloat16* Alo = g_axlo + (size_t)z * XSZ;
    const __nv_bfloat16* Bhi = g_w2hi + (size_t)z * WSZ;
    const __nv_bfloat16* Blo = g_w2lo + (size_t)z * WSZ;
    const float* bias = (z == 0) ? bq : (z == 1) ? bk : bv;

    float acc[4][4][4] = {};
    gemm_core(acc, sm, sb, tid, wr, wc, lid, m0, n0, Ahi, Alo, Bhi, Blo);

    #pragma unroll
    for (int mt = 0; mt < 4; mt++) {
        #pragma unroll
        for (int nt = 0; nt < 4; nt++) {
            int col = n0 + wc * 32 + nt * 8 + (lid & 3) * 2;
            float2 bvv = *(const float2*)(bias + col);
            int r0 = m0 + wr * 64 + mt * 16 + (lid >> 2);
            #pragma unroll
            for (int half = 0; half < 2; half++) {
                int r = r0 + half * 8;
                float ox = acc[mt][nt][half * 2 + 0] + bvv.x;
                float oy = acc[mt][nt][half * 2 + 1] + bvv.y;
                int b = r >> 11, s = r & (SS - 1);
                int hh = col >> 6, hd = col & 63;
                size_t off = (((size_t)(b * HH + hh)) * SS + s) * HDIM + hd;
                uint32_t ph, pl;
                split_pair(ox, oy, ph, pl);
                if (z == 0) {
                    *(uint32_t*)(g_qhi + off) = ph;
                } else if (z == 1) {
                    *(uint32_t*)(g_khi + off) = ph;
                } else {
                    *(uint32_t*)(g_vhi + off) = ph;
                    *(uint32_t*)(g_vlo + off) = pl;
                }
            }
        }
    }
}

__global__ __launch_bounds__(256) void oproj_tc(
    const float* __restrict__ bias, float* __restrict__ outp)
{
    extern __shared__ __align__(16) char sm[];
    const int tid = threadIdx.x, wid = tid >> 5, lid = tid & 31;
    const int n0 = blockIdx.x * 128, m0 = blockIdx.y * 128;
    const int wr = wid & 1, wc = wid >> 1;
    const uint32_t sb = smem_u32(sm);

    float acc[4][4][4] = {};
    gemm_core(acc, sm, sb, tid, wr, wc, lid, m0, n0,
              g_xhi, g_xlo, g_w2hi + 3 * (size_t)WSZ, g_w2lo + 3 * (size_t)WSZ);

    #pragma unroll
    for (int mt = 0; mt < 4; mt++) {
        #pragma unroll
        for (int nt = 0; nt < 4; nt++) {
            int col = n0 + wc * 32 + nt * 8 + (lid & 3) * 2;
            float2 bvv = *(const float2*)(bias + col);
            int r0 = m0 + wr * 64 + mt * 16 + (lid >> 2);
            #pragma unroll
            for (int half = 0; half < 2; half++) {
                int r = r0 + half * 8;
                float2 o;
                o.x = acc[mt][nt][half * 2 + 0] + bvv.x;
                o.y = acc[mt][nt][half * 2 + 1] + bvv.y;
                *(float2*)(outp + (size_t)r * DD + col) = o;
            }
        }
    }
}

// ---------------- flash attention: kt-chunk 64, 2 CTAs/SM ------------------
// sf shrinks 64->32 regs; P packed per-ks (no persistent aPhi/aPlo arrays).
// Smem: Q 128x64 (18432) + K 64x64 (9216) + Vhi/Vlo 64x64 (9216 each).
#define QROWB 144
#define VROW2 144
#define OFF_QHI 0
#define OFF_KHI 18432
#define OFF_VHI 27648
#define OFF_VLO 36864
#define SMEM_FLASH 46080

__global__ __launch_bounds__(256, 2) void flash_mma()
{
    extern __shared__ __align__(16) char sm[];
    const int tid = threadIdx.x, wid = tid >> 5, lid = tid & 31;
    const int q0 = blockIdx.x * 128, h = blockIdx.y, b = blockIdx.z;
    const size_t base = ((size_t)(b * HH + h)) * SS * HDIM;
    const float cf = 0.18033688f;   // 0.125 * log2(e)

    // Q tile 128x64 (hi only), full 128B rows via uint4
    #pragma unroll
    for (int i = 0; i < 4; i++) {
        int idx = tid + i * 256, row = idx >> 3, g = idx & 7;
        size_t src = base + (size_t)(q0 + row) * HDIM + g * 8;
        *(uint4*)(sm + OFF_QHI + row * QROWB + g * 16) = *(const uint4*)(g_qhi + src);
    }
    __syncthreads();

    uint32_t aQh[4][4];
    const int qrb = (wid * 16 + (lid >> 2)) * QROWB + (lid & 3) * 4;
    #pragma unroll
    for (int ks = 0; ks < 4; ks++) {
        const char* p = sm + OFF_QHI + qrb + ks * 32;
        aQh[ks][0] = *(const uint32_t*)(p);
        aQh[ks][1] = *(const uint32_t*)(p + 8 * QROWB);
        aQh[ks][2] = *(const uint32_t*)(p + 16);
        aQh[ks][3] = *(const uint32_t*)(p + 8 * QROWB + 16);
    }

    float acc[8][4] = {};
    float mrow[2] = {-1e30f, -1e30f}, lrow[2] = {0.f, 0.f};

    for (int kt0 = 0; kt0 < SS; kt0 += 64) {
        __syncthreads();

        // K chunk: 64 rows x 64 dims (hi only)
        #pragma unroll
        for (int i = 0; i < 2; i++) {
            int idx = tid + i * 256, row = idx >> 3, g = idx & 7;
            size_t src = base + (size_t)(kt0 + row) * HDIM + g * 8;
            *(uint4*)(sm + OFF_KHI + row * QROWB + g * 16) = *(const uint4*)(g_khi + src);
        }
        // V chunk transposed (hi/lo): 64 kt. Warp spans 4 g x 8 kt
        // (g = idx[1:0]|idx[9:8]<<2, kt = idx[7:2]) -> ~8 banks.
        #pragma unroll
        for (int i = 0; i < 4; i++) {
            int idx = tid + i * 256;
            int g  = (idx & 3) | (((idx >> 8) & 3) << 2);
            int kt = (idx >> 2) & 63;
            size_t src = base + (size_t)(kt0 + kt) * HDIM + g * 4;
            uint2 vh = *(const uint2*)(g_vhi + src);
            uint2 vl = *(const uint2*)(g_vlo + src);
            #pragma unroll
            for (int j = 0; j < 4; j++) {
                uint16_t hv = (j < 2) ? (uint16_t)(vh.x >> (j * 16))
                                      : (uint16_t)(vh.y >> ((j - 2) * 16));
                uint16_t lv = (j < 2) ? (uint16_t)(vl.x >> (j * 16))
                                      : (uint16_t)(vl.y >> ((j - 2) * 16));
                *(uint16_t*)(sm + OFF_VHI + (g * 4 + j) * VROW2 + kt * 2) = hv;
                *(uint16_t*)(sm + OFF_VLO + (g * 4 + j) * VROW2 + kt * 2) = lv;
            }
        }
        __syncthreads();

        // S = Qhi Khi^T (single pass), 8 n-tiles x 4 k-steps
        float sf[8][4];
        #pragma unroll
        for (int nt = 0; nt < 8; nt++)
            sf[nt][0] = sf[nt][1] = sf[nt][2] = sf[nt][3] = 0.f;
        #pragma unroll
        for (int nt = 0; nt < 8; nt++) {
            #pragma unroll
            for (int ks = 0; ks < 4; ks++) {
                const char* p = sm + OFF_KHI +
                    (nt * 8 + (lid >> 2)) * QROWB + ks * 32 + (lid & 3) * 4;
                uint32_t bf[2] = { *(const uint32_t*)p, *(const uint32_t*)(p + 16) };
                mma16816(sf[nt], aQh[ks], bf);
            }
        }

        // online softmax
        float corr[2];
        #pragma unroll
        for (int half = 0; half < 2; half++) {
            const int v0 = half * 2, v1 = half * 2 + 1;
            float tm = -1e30f;
            #pragma unroll
            for (int nt = 0; nt < 8; nt++)
                tm = fmaxf(tm, fmaxf(sf[nt][v0], sf[nt][v1]));
            tm = fmaxf(tm, __shfl_xor_sync(0xffffffffu, tm, 1));
            tm = fmaxf(tm, __shfl_xor_sync(0xffffffffu, tm, 2));
            float mn = fmaxf(mrow[half], tm * cf);
            corr[half] = fast_exp2(mrow[half] - mn);
            mrow[half] = mn;
            float sum = 0.f;
            #pragma unroll
            for (int nt = 0; nt < 8; nt++) {
                float p0 = fast_exp2(fmaf(sf[nt][v0], cf, -mn));
                float p1 = fast_exp2(fmaf(sf[nt][v1], cf, -mn));
                sf[nt][v0] = p0; sf[nt][v1] = p1;
                sum += p0 + p1;
            }
            sum += __shfl_xor_sync(0xffffffffu, sum, 1);
            sum += __shfl_xor_sync(0xffffffffu, sum, 2);
            lrow[half] = lrow[half] * corr[half] + sum;
        }
        #pragma unroll
        for (int nt = 0; nt < 8; nt++) {
            acc[nt][0] *= corr[0]; acc[nt][1] *= corr[0];
            acc[nt][2] *= corr[1]; acc[nt][3] *= corr[1];
        }

        // PV: ks-fused pack (aP built per k-step, 8 regs live) + 3-pass mma
        #pragma unroll
        for (int ks = 0; ks < 4; ks++) {
            uint32_t aPh[4], aPl[4];
            split_pair(sf[2*ks  ][0], sf[2*ks  ][1], aPh[0], aPl[0]);
            split_pair(sf[2*ks  ][2], sf[2*ks  ][3], aPh[1], aPl[1]);
            split_pair(sf[2*ks+1][0], sf[2*ks+1][1], aPh[2], aPl[2]);
            split_pair(sf[2*ks+1][2], sf[2*ks+1][3], aPh[3], aPl[3]);
            #pragma unroll
            for (int nt = 0; nt < 8; nt++) {
                const char* ph = sm + OFF_VHI +
                    (nt * 8 + (lid >> 2)) * VROW2 + ks * 32 + (lid & 3) * 4;
                uint32_t bh[2] = { *(const uint32_t*)ph, *(const uint32_t*)(ph + 16) };
                mma16816(acc[nt], aPh, bh);
                mma16816(acc[nt], aPl, bh);
                const char* pl = sm + OFF_VLO +
                    (nt * 8 + (lid >> 2)) * VROW2 + ks * 32 + (lid & 3) * 4;
                uint32_t bl[2] = { *(const uint32_t*)pl, *(const uint32_t*)(pl + 16) };
                mma16816(acc[nt], aPh, bl);
            }
        }
    }

    // epilogue: normalize, split, write ctx hi/lo row-major [M, D]
    float inv0 = 1.0f / lrow[0], inv1 = 1.0f / lrow[1];
    int r0 = q0 + wid * 16 + (lid >> 2);
    size_t m0 = (size_t)(b * SS + r0) * DD + h * HDIM;
    #pragma unroll
    for (int nt = 0; nt < 8; nt++) {
        int d = nt * 8 + 2 * (lid & 3);
        uint32_t ph, pl;
        split_pair(acc[nt][0] * inv0, acc[nt][1] * inv0, ph, pl);
        *(uint32_t*)(g_xhi + m0 + d) = ph;
        *(uint32_t*)(g_xlo + m0 + d) = pl;
        split_pair(acc[nt][2] * inv1, acc[nt][3] * inv1, ph, pl);
        *(uint32_t*)(g_xhi + m0 + 8 * DD + d) = ph;
        *(uint32_t*)(g_xlo + m0 + 8 * DD + d) = pl;
    }
}

// ---------------------------------------------------------------------------
extern "C" void kernel_launch(void* const* d_in, const int* in_sizes, int n_in,
                              void* d_out, int out_size)
{
    const float* Q  = (const float*)d_in[0];
    const float* K  = (const float*)d_in[1];
    const float* V  = (const float*)d_in[2];
    const float* Wq = (const float*)d_in[3];
    const float* bq = (const float*)d_in[4];
    const float* Wk = (const float*)d_in[5];
    const float* bk = (const float*)d_in[6];
    const float* Wv = (const float*)d_in[7];
    const float* bv = (const float*)d_in[8];
    const float* Wo = (const float*)d_in[9];
    const float* bo = (const float*)d_in[10];
    float* out = (float*)d_out;

    cudaFuncSetAttribute(proj_tc,   cudaFuncAttributeMaxDynamicSharedMemorySize, SMEM_G2);
    cudaFuncSetAttribute(oproj_tc,  cudaFuncAttributeMaxDynamicSharedMemorySize, SMEM_G2);
    cudaFuncSetAttribute(flash_mma, cudaFuncAttributeMaxDynamicSharedMemorySize, SMEM_FLASH);

    const int x4 = XSZ / 4;
    const int w4 = WSZ / 4;

    convert_act<<<dim3(x4 / 256, 3), 256>>>(Q, K, V, x4);
    convert_w<<<dim3(w4 / 256, 4), 256>>>(Wq, Wk, Wv, Wo, w4);

    proj_tc<<<dim3(DD / 128, MTOT / 128, 3), 256, SMEM_G2>>>(bq, bk, bv);

    flash_mma<<<dim3(SS / 128, HH, BB), 256, SMEM_FLASH>>>();

    oproj_tc<<<dim3(DD / 128, MTOT / 128), 256, SMEM_G2>>>(bo, out);
}